// round 1
// baseline (speedup 1.0000x reference)
#include <cuda_runtime.h>
#include <math.h>

// Problem dims
#define NSITE 524288          // 32*32*32*16
#define LM    64
#define MD    128
#define TILE  32              // sites per block-iteration
#define NT    256             // threads per block
#define GRID_MLP 148          // one persistent block per SM (B200)

// 2MB scratch for x_nn (static device global: allowed)
__device__ float g_nn[NSITE];

// ---------------- f32x2 packed-FMA helpers (sm_100+) ----------------
static __device__ __forceinline__ unsigned long long pack2(float lo, float hi) {
    unsigned long long r;
    asm("mov.b64 %0, {%1,%2};" : "=l"(r) : "f"(lo), "f"(hi));
    return r;
}
static __device__ __forceinline__ void unpack2(unsigned long long v, float& lo, float& hi) {
    asm("mov.b64 {%0,%1}, %2;" : "=f"(lo), "=f"(hi) : "l"(v));
}
static __device__ __forceinline__ unsigned long long ffma2(
    unsigned long long a, unsigned long long b, unsigned long long c) {
    unsigned long long d;
    asm("fma.rn.f32x2 %0, %1, %2, %3;" : "=l"(d) : "l"(a), "l"(b), "l"(c));
    return d;
}

// ---------------- one dense layer: sOut[32x128] = tanh(sIn[32xK] @ sWT[Kx128] + sB) ----
// Thread tile: 4 sites x 4 hidden (as 2 f32x2 pairs). Warp = 4 sites (broadcast A),
// lanes cover 128 hidden via float4/ulonglong2 (conflict-free).
template<int K>
static __device__ __forceinline__ void layer_gemm_tanh(
    const float* __restrict__ sIn, const float* __restrict__ sWT,
    const float* __restrict__ sB, float* __restrict__ sOut, int tid)
{
    const int s0 = (tid >> 5) * 4;   // warp -> 4 sites
    const int n0 = (tid & 31) * 4;   // lane -> 4 hidden units

    unsigned long long accx[4], accy[4];
    const unsigned long long bx = pack2(sB[n0],   sB[n0+1]);
    const unsigned long long by = pack2(sB[n0+2], sB[n0+3]);
#pragma unroll
    for (int i = 0; i < 4; i++) { accx[i] = bx; accy[i] = by; }

    const float* a0p = sIn + s0 * K;
#pragma unroll 8
    for (int k = 0; k < K; k++) {
        unsigned long long pa[4];
#pragma unroll
        for (int i = 0; i < 4; i++) { float a = a0p[i * K + k]; pa[i] = pack2(a, a); }
        ulonglong2 bv = *reinterpret_cast<const ulonglong2*>(sWT + k * 128 + n0);
#pragma unroll
        for (int i = 0; i < 4; i++) {
            accx[i] = ffma2(pa[i], bv.x, accx[i]);
            accy[i] = ffma2(pa[i], bv.y, accy[i]);
        }
    }

    float4 r[4];
#pragma unroll
    for (int i = 0; i < 4; i++) {
        float f0, f1, f2, f3;
        unpack2(accx[i], f0, f1);
        unpack2(accy[i], f2, f3);
        r[i] = make_float4(tanhf(f0), tanhf(f1), tanhf(f2), tanhf(f3));
    }
    __syncthreads();   // all reads of sIn done (needed when sOut aliases sIn)
#pragma unroll
    for (int i = 0; i < 4; i++)
        *reinterpret_cast<float4*>(sOut + (s0 + i) * 128 + n0) = r[i];
    __syncthreads();   // sOut visible to everyone
}

// ---------------- layer 3: scalar head. 8 lanes per site, shfl-reduce. --------------
static __device__ __forceinline__ float layer3_val(
    const float* __restrict__ sH, const float* __restrict__ sW3,
    float b3, float maxos, int tid)
{
    const int s  = tid >> 3;
    const int m0 = (tid & 7) * 16;
    const float4* h4 = reinterpret_cast<const float4*>(sH + s * 128 + m0);
    const float4* w4 = reinterpret_cast<const float4*>(sW3 + m0);
    float sum = 0.f;
#pragma unroll
    for (int j = 0; j < 4; j++) {
        float4 h = h4[j], w = w4[j];
        sum += h.x * w.x + h.y * w.y + h.z * w.z + h.w * w.w;
    }
    sum += __shfl_down_sync(0xffffffffu, sum, 4);
    sum += __shfl_down_sync(0xffffffffu, sum, 2);
    sum += __shfl_down_sync(0xffffffffu, sum, 1);
    return tanhf(sum + b3) * maxos;   // valid on lanes with (tid & 7) == 0
}

// ---------------- main fused MLP kernel (persistent, all weights in SMEM) -----------
__global__ __launch_bounds__(NT, 1)
void fnn_mlp_kernel(
    const float* __restrict__ x_in, const float* __restrict__ weight,
    const float* __restrict__ ag,
    const float* __restrict__ W1,  const float* __restrict__ b1,
    const float* __restrict__ W2,  const float* __restrict__ b2,
    const float* __restrict__ W3,  const float* __restrict__ b3,
    const float* __restrict__ W1n, const float* __restrict__ b1n,
    const float* __restrict__ W2n, const float* __restrict__ b2n,
    const float* __restrict__ W3n, const float* __restrict__ b3n,
    const float* __restrict__ max_os_l,
    float* __restrict__ out_os)
{
    extern __shared__ float sm[];
    float* sW1T  = sm;                 // 64x128  = 8192
    float* sW2T  = sW1T  + 8192;       // 128x128 = 16384
    float* sW1nT = sW2T  + 16384;      // 8192
    float* sW2nT = sW1nT + 8192;       // 16384
    float* sA    = sW2nT + 16384;      // 32x64   = 2048
    float* sH    = sA    + 2048;       // 32x128  = 4096
    float* sB1   = sH    + 4096;       // 128
    float* sB2   = sB1   + 128;
    float* sB1n  = sB2   + 128;
    float* sB2n  = sB1n  + 128;
    float* sW3   = sB2n  + 128;
    float* sW3n  = sW3   + 128;
    float* sAr   = sW3n  + 128;        // 32
    float* sOS   = sAr   + 32;         // 32

    const int tid = threadIdx.x;

    // one-time staging: transposed weights + biases
    for (int idx = tid; idx < 8192; idx += NT) {
        int m = idx >> 6, l = idx & 63;
        sW1T [l * 128 + m] = W1 [idx];
        sW1nT[l * 128 + m] = W1n[idx];
    }
    for (int idx = tid; idx < 16384; idx += NT) {
        int n = idx >> 7, k = idx & 127;
        sW2T [k * 128 + n] = W2 [idx];
        sW2nT[k * 128 + n] = W2n[idx];
    }
    if (tid < 128) {
        sB1[tid] = b1[tid];  sB2[tid] = b2[tid];
        sB1n[tid] = b1n[tid]; sB2n[tid] = b2n[tid];
        sW3[tid] = W3[tid];  sW3n[tid] = W3n[tid];
    }
    const float maxos = expf(max_os_l[0]);
    const float b3v = b3[0], b3nv = b3n[0];

    const int sL = tid >> 3;          // site-in-tile this thread stages
    const int lb = (tid & 7) * 8;     // 8-feature chunk
    float agv[8], wtv[8];
#pragma unroll
    for (int j = 0; j < 8; j++) { agv[j] = ag[lb + j]; wtv[j] = weight[lb + j]; }
    __syncthreads();

    for (int tile = blockIdx.x; tile < NSITE / TILE; tile += gridDim.x) {
        const int base = tile * TILE;

        // stage x*weight into sA; compute AR dot (raw x . ag) on the fly
        const float4* xp = reinterpret_cast<const float4*>(
            x_in + (size_t)(base + sL) * LM + lb);
        float4 v0 = xp[0], v1 = xp[1];
        float arp = v0.x*agv[0] + v0.y*agv[1] + v0.z*agv[2] + v0.w*agv[3]
                  + v1.x*agv[4] + v1.y*agv[5] + v1.z*agv[6] + v1.w*agv[7];
        float* ap = sA + sL * LM + lb;
        *reinterpret_cast<float4*>(ap) =
            make_float4(v0.x*wtv[0], v0.y*wtv[1], v0.z*wtv[2], v0.w*wtv[3]);
        *reinterpret_cast<float4*>(ap + 4) =
            make_float4(v1.x*wtv[4], v1.y*wtv[5], v1.z*wtv[6], v1.w*wtv[7]);
        arp += __shfl_down_sync(0xffffffffu, arp, 4);
        arp += __shfl_down_sync(0xffffffffu, arp, 2);
        arp += __shfl_down_sync(0xffffffffu, arp, 1);
        if ((tid & 7) == 0) sAr[sL] = arp;
        __syncthreads();

        // onsite MLP
        layer_gemm_tanh<64 >(sA, sW1T, sB1, sH, tid);
        layer_gemm_tanh<128>(sH, sW2T, sB2, sH, tid);
        float osv = layer3_val(sH, sW3, b3v, maxos, tid);
        if ((tid & 7) == 0) sOS[tid >> 3] = osv;

        // nearest-neighbor MLP (same sA input; sH reads complete before overwrite
        // because the next gemm's internal __syncthreads precedes its sH writes)
        layer_gemm_tanh<64 >(sA, sW1nT, sB1n, sH, tid);
        layer_gemm_tanh<128>(sH, sW2nT, sB2n, sH, tid);
        float nnv = layer3_val(sH, sW3n, b3nv, maxos, tid);

        if ((tid & 7) == 0) {
            int s = tid >> 3;
            g_nn[base + s]   = nnv;
            out_os[base + s] = sOS[s] + sAr[s];
        }
        __syncthreads();   // protect sA/sAr/sOS before next tile's staging
    }
}

// ---------------- stencil + sigma kernel --------------------------------------------
__global__ void fnn_stencil_kernel(const float* __restrict__ sigma_l,
                                   float* __restrict__ out)
{
    int idx = blockIdx.x * blockDim.x + threadIdx.x;
    if (idx >= NSITE) return;
    const int ib = idx & 15;
    const int iz = (idx >> 4)  & 31;
    const int iy = (idx >> 9)  & 31;
    const int ix = (idx >> 14) & 31;
    const int xm = (ix + 31) & 31, xp = (ix + 1) & 31;
    const int ym = (iy + 31) & 31, yp = (iy + 1) & 31;
    const int zm = (iz + 31) & 31, zp = (iz + 1) & 31;

#define FNN_I(a, b, c) ((((((a) << 5) + (b)) << 5) + (c)) * 16 + ib)
    float s =
        g_nn[FNN_I(xm, iy, zm)] + g_nn[FNN_I(xm, iy, zp)] +
        g_nn[FNN_I(xp, iy, zm)] + g_nn[FNN_I(xp, iy, zp)] +
        g_nn[FNN_I(ix, ym, zm)] + g_nn[FNN_I(ix, ym, zp)] +
        g_nn[FNN_I(ix, yp, zm)] + g_nn[FNN_I(ix, yp, zp)];
#undef FNN_I

    out[idx] += 0.125f * s;
    out[NSITE + idx] = expf(sigma_l[0]);
}

// ---------------- launch --------------------------------------------------------------
extern "C" void kernel_launch(void* const* d_in, const int* in_sizes, int n_in,
                              void* d_out, int out_size)
{
    const float* x_in     = (const float*)d_in[0];
    const float* weight   = (const float*)d_in[1];
    const float* ag       = (const float*)d_in[2];
    const float* W1       = (const float*)d_in[3];
    const float* b1       = (const float*)d_in[4];
    const float* W2       = (const float*)d_in[5];
    const float* b2       = (const float*)d_in[6];
    const float* W3       = (const float*)d_in[7];
    const float* b3       = (const float*)d_in[8];
    const float* W1n      = (const float*)d_in[9];
    const float* b1n      = (const float*)d_in[10];
    const float* W2n      = (const float*)d_in[11];
    const float* b2n      = (const float*)d_in[12];
    const float* W3n      = (const float*)d_in[13];
    const float* b3n      = (const float*)d_in[14];
    const float* max_os_l = (const float*)d_in[15];
    const float* sigma_l  = (const float*)d_in[16];
    float* out = (float*)d_out;

    // 56128 floats = 224512 bytes of dynamic SMEM
    const size_t smem = 56128 * sizeof(float);
    cudaFuncSetAttribute(fnn_mlp_kernel,
                         cudaFuncAttributeMaxDynamicSharedMemorySize, (int)smem);

    fnn_mlp_kernel<<<GRID_MLP, NT, smem>>>(
        x_in, weight, ag, W1, b1, W2, b2, W3, b3,
        W1n, b1n, W2n, b2n, W3n, b3n, max_os_l, out);

    fnn_stencil_kernel<<<NSITE / 256, 256>>>(sigma_l, out);
}

// round 4
// speedup vs baseline: 3.1549x; 3.1549x over previous
#include <cuda_runtime.h>
#include <cstdint>
#include <math.h>

#define NSITE 524288          // 32*32*32*16
#define TILE  128
#define NTILES (NSITE / TILE) // 4096
#define NT    256             // 8 warps
#define GRID  148

#define XS 68                 // X row stride (floats), conflict-free frag reads
#define WS 68                 // staged W1 row stride
#define HS 132                // H row stride

// SMEM float offsets
#define SX_OFF  0
#define SW1_OFF 8704          // 128*68
#define SH_OFF  26112         // + 256*68
#define SP_OFF  43008         // + 128*132
#define SMEM_FLOATS 44032     // + 8*128
#define SMEM_BYTES (SMEM_FLOATS * 4)

__device__ float g_nn[NSITE];
__device__ __align__(16) float  g_b1ext[256];   // [b1 ; b1n]
__device__ __align__(16) float2 g_c2 [128];     // (b2[n],  w3[n])
__device__ __align__(16) float2 g_c2n[128];     // (b2n[n], w3n[n])

static __device__ __forceinline__ uint32_t f2tf(float x) {
    uint32_t r; asm("cvt.rna.tf32.f32 %0, %1;" : "=r"(r) : "f"(x)); return r;
}
static __device__ __forceinline__ float tanha(float x) {
    float y; asm("tanh.approx.f32 %0, %1;" : "=f"(y) : "f"(x)); return y;
}
static __device__ __forceinline__ void mma_tf32(
    float& c0, float& c1, float& c2, float& c3,
    uint32_t a0, uint32_t a1, uint32_t a2, uint32_t a3,
    uint32_t b0, uint32_t b1)
{
    asm volatile(
        "mma.sync.aligned.m16n8k8.row.col.f32.tf32.tf32.f32 "
        "{%0,%1,%2,%3}, {%4,%5,%6,%7}, {%8,%9}, {%0,%1,%2,%3};"
        : "+f"(c0), "+f"(c1), "+f"(c2), "+f"(c3)
        : "r"(a0), "r"(a1), "r"(a2), "r"(a3), "r"(b0), "r"(b1));
}

__global__ __launch_bounds__(NT, 1)
void fnn_mma_kernel(
    const float* __restrict__ x_in, const float* __restrict__ weight,
    const float* __restrict__ ag,
    const float* __restrict__ W1,  const float* __restrict__ b3,
    const float* __restrict__ W2,
    const float* __restrict__ W1n, const float* __restrict__ b3n,
    const float* __restrict__ W2n,
    const float* __restrict__ max_os_l,
    float* __restrict__ out_os)
{
    extern __shared__ float sm[];
    float* sX  = sm + SX_OFF;
    float* sW1 = sm + SW1_OFF;
    float* sH  = sm + SH_OFF;
    float* sP  = sm + SP_OFF;

    const int tid = threadIdx.x;
    const int wid = tid >> 5;
    const int lid = tid & 31;
    const int g   = lid >> 2;      // groupID (row within fragment)
    const int t   = lid & 3;       // threadID_in_group (col/k within fragment)

    // ---- one-time: stage [W1;W1n] * diag(weight), tf32-rounded ----
    for (int idx = tid; idx < 16384; idx += NT) {
        int n = idx >> 6, k = idx & 63;
        float v = (n < 128 ? W1[n * 64 + k] : W1n[(n - 128) * 64 + k]) * weight[k];
        sW1[n * WS + k] = __uint_as_float(f2tf(v));
    }
    const float maxos = expf(max_os_l[0]);
    const float b3v = b3[0], b3nv = b3n[0];
    __syncthreads();

    for (int tile = blockIdx.x; tile < NTILES; tile += GRID) {
        const int base = tile * TILE;

        // ---- stage X tile, tf32-rounded ----
        #pragma unroll
        for (int it = 0; it < 8; it++) {
            int e = tid + it * NT;          // 2048 float4
            int row = e >> 4, col = (e & 15) << 2;
            float4 v = *(const float4*)(x_in + (size_t)(base + row) * 64 + col);
            uint4 u = make_uint4(f2tf(v.x), f2tf(v.y), f2tf(v.z), f2tf(v.w));
            *(uint4*)(sX + row * XS + col) = u;
        }
        __syncthreads();

        for (int mlp = 0; mlp < 2; mlp++) {
            const float* Wg2   = mlp ? W2n : W2;
            const float* b1p   = g_b1ext + mlp * 128;
            const float* c2p   = (const float*)(mlp ? g_c2n : g_c2);
            const int    w1off = mlp * 128;

            // ======== GEMM1: H = tanh(X @ W1'^T + b1), K=64 ========
            // preload B frags for this warp's 2 n-tiles
            uint32_t B1r[2][16];
            #pragma unroll
            for (int j = 0; j < 2; j++) {
                int n0 = (wid * 2 + j) * 8;
                const float* wp = sW1 + (w1off + n0 + g) * WS;
                #pragma unroll
                for (int ks = 0; ks < 8; ks++) {
                    B1r[j][ks*2+0] = __float_as_uint(wp[ks*8 + t]);
                    B1r[j][ks*2+1] = __float_as_uint(wp[ks*8 + t + 4]);
                }
            }
            #pragma unroll
            for (int m = 0; m < 8; m++) {
                const int m0 = m * 16;
                uint32_t Ar[32];
                const float* xr0 = sX + (m0 + g) * XS;
                const float* xr1 = sX + (m0 + g + 8) * XS;
                #pragma unroll
                for (int ks = 0; ks < 8; ks++) {
                    Ar[ks*4+0] = __float_as_uint(xr0[ks*8 + t]);
                    Ar[ks*4+1] = __float_as_uint(xr1[ks*8 + t]);
                    Ar[ks*4+2] = __float_as_uint(xr0[ks*8 + t + 4]);
                    Ar[ks*4+3] = __float_as_uint(xr1[ks*8 + t + 4]);
                }
                #pragma unroll
                for (int j = 0; j < 2; j++) {
                    float c0=0.f, c1=0.f, c2=0.f, c3=0.f;
                    #pragma unroll
                    for (int ks = 0; ks < 8; ks++)
                        mma_tf32(c0,c1,c2,c3, Ar[ks*4],Ar[ks*4+1],Ar[ks*4+2],Ar[ks*4+3],
                                 B1r[j][ks*2], B1r[j][ks*2+1]);
                    int n0 = (wid * 2 + j) * 8;
                    float2 bv = *(const float2*)(b1p + n0 + 2*t);
                    uint32_t h0 = f2tf(tanha(c0 + bv.x));
                    uint32_t h1 = f2tf(tanha(c1 + bv.y));
                    uint32_t h2 = f2tf(tanha(c2 + bv.x));
                    uint32_t h3 = f2tf(tanha(c3 + bv.y));
                    *(uint2*)(sH + (m0 + g    ) * HS + n0 + 2*t) = make_uint2(h0, h1);
                    *(uint2*)(sH + (m0 + g + 8) * HS + n0 + 2*t) = make_uint2(h2, h3);
                }
            }
            __syncthreads();

            // ======== GEMM2: head partials, K=128 ========
            uint32_t B2r[2][32];
            #pragma unroll
            for (int j = 0; j < 2; j++) {
                int n0 = (wid * 2 + j) * 8;
                const float* wp = Wg2 + (size_t)(n0 + g) * 128;
                #pragma unroll
                for (int ks = 0; ks < 16; ks++) {
                    B2r[j][ks*2+0] = f2tf(__ldg(wp + ks*8 + t));
                    B2r[j][ks*2+1] = f2tf(__ldg(wp + ks*8 + t + 4));
                }
            }
            #pragma unroll
            for (int m = 0; m < 8; m++) {
                const int m0 = m * 16;
                uint32_t Ar[64];
                const float* hr0 = sH + (m0 + g) * HS;
                const float* hr1 = sH + (m0 + g + 8) * HS;
                #pragma unroll
                for (int ks = 0; ks < 16; ks++) {
                    Ar[ks*4+0] = __float_as_uint(hr0[ks*8 + t]);
                    Ar[ks*4+1] = __float_as_uint(hr1[ks*8 + t]);
                    Ar[ks*4+2] = __float_as_uint(hr0[ks*8 + t + 4]);
                    Ar[ks*4+3] = __float_as_uint(hr1[ks*8 + t + 4]);
                }
                float sum0 = 0.f, sum1 = 0.f;
                #pragma unroll
                for (int j = 0; j < 2; j++) {
                    float c0=0.f, c1=0.f, c2=0.f, c3=0.f;
                    #pragma unroll
                    for (int ks = 0; ks < 16; ks++)
                        mma_tf32(c0,c1,c2,c3, Ar[ks*4],Ar[ks*4+1],Ar[ks*4+2],Ar[ks*4+3],
                                 B2r[j][ks*2], B2r[j][ks*2+1]);
                    int n0 = (wid * 2 + j) * 8;
                    float4 cw = *(const float4*)(c2p + (n0 + 2*t) * 2); // (b2,w3,b2',w3')
                    sum0 += tanha(c0 + cw.x) * cw.y + tanha(c1 + cw.z) * cw.w;
                    sum1 += tanha(c2 + cw.x) * cw.y + tanha(c3 + cw.z) * cw.w;
                }
                sum0 += __shfl_xor_sync(0xffffffffu, sum0, 1);
                sum0 += __shfl_xor_sync(0xffffffffu, sum0, 2);
                sum1 += __shfl_xor_sync(0xffffffffu, sum1, 1);
                sum1 += __shfl_xor_sync(0xffffffffu, sum1, 2);
                if (t == 0) {
                    sP[wid * 128 + m0 + g]     = sum0;
                    sP[wid * 128 + m0 + g + 8] = sum1;
                }
            }
            __syncthreads();

            // ======== head: combine 8 warp partials ========
            if (tid < 128) {
                float s = 0.f;
                #pragma unroll
                for (int w = 0; w < 8; w++) s += sP[w * 128 + tid];
                if (mlp == 0) {
                    float ar = 0.f;
                    #pragma unroll
                    for (int q = 0; q < 16; q++) {
                        float4 xv = *(const float4*)(sX + tid * XS + q * 4);
                        float4 av = __ldg((const float4*)(ag + q * 4));
                        ar += xv.x*av.x + xv.y*av.y + xv.z*av.z + xv.w*av.w;
                    }
                    out_os[base + tid] = tanhf(s + b3v) * maxos + ar;
                } else {
                    g_nn[base + tid] = tanhf(s + b3nv) * maxos;
                }
            }
            __syncthreads();
        }
    }
}

// ---- prep: pack per-column constants ----
__global__ void fnn_prep_kernel(
    const float* __restrict__ b1, const float* __restrict__ b1n,
    const float* __restrict__ b2, const float* __restrict__ w3,
    const float* __restrict__ b2n, const float* __restrict__ w3n)
{
    int n = threadIdx.x;   // 128
    g_b1ext[n]       = b1[n];
    g_b1ext[128 + n] = b1n[n];
    g_c2 [n] = make_float2(b2[n],  w3[n]);
    g_c2n[n] = make_float2(b2n[n], w3n[n]);
}

// ---- stencil + sigma ----
__global__ void fnn_stencil_kernel(const float* __restrict__ sigma_l,
                                   float* __restrict__ out)
{
    int idx = blockIdx.x * blockDim.x + threadIdx.x;
    if (idx >= NSITE) return;
    const int ib = idx & 15;
    const int iz = (idx >> 4)  & 31;
    const int iy = (idx >> 9)  & 31;
    const int ix = (idx >> 14) & 31;
    const int xm = (ix + 31) & 31, xp = (ix + 1) & 31;
    const int ym = (iy + 31) & 31, yp = (iy + 1) & 31;
    const int zm = (iz + 31) & 31, zp = (iz + 1) & 31;
#define FNN_I(a, b, c) ((((((a) << 5) + (b)) << 5) + (c)) * 16 + ib)
    float s =
        g_nn[FNN_I(xm, iy, zm)] + g_nn[FNN_I(xm, iy, zp)] +
        g_nn[FNN_I(xp, iy, zm)] + g_nn[FNN_I(xp, iy, zp)] +
        g_nn[FNN_I(ix, ym, zm)] + g_nn[FNN_I(ix, ym, zp)] +
        g_nn[FNN_I(ix, yp, zm)] + g_nn[FNN_I(ix, yp, zp)];
#undef FNN_I
    out[idx] += 0.125f * s;
    out[NSITE + idx] = expf(sigma_l[0]);
}

extern "C" void kernel_launch(void* const* d_in, const int* in_sizes, int n_in,
                              void* d_out, int out_size)
{
    const float* x_in     = (const float*)d_in[0];
    const float* weight   = (const float*)d_in[1];
    const float* ag       = (const float*)d_in[2];
    const float* W1       = (const float*)d_in[3];
    const float* b1       = (const float*)d_in[4];
    const float* W2       = (const float*)d_in[5];
    const float* b2       = (const float*)d_in[6];
    const float* W3       = (const float*)d_in[7];
    const float* b3       = (const float*)d_in[8];
    const float* W1n      = (const float*)d_in[9];
    const float* b1n      = (const float*)d_in[10];
    const float* W2n      = (const float*)d_in[11];
    const float* b2n      = (const float*)d_in[12];
    const float* W3n      = (const float*)d_in[13];
    const float* b3n      = (const float*)d_in[14];
    const float* max_os_l = (const float*)d_in[15];
    const float* sigma_l  = (const float*)d_in[16];
    float* out = (float*)d_out;

    fnn_prep_kernel<<<1, 128>>>(b1, b1n, b2, W3, b2n, W3n);

    cudaFuncSetAttribute(fnn_mma_kernel,
                         cudaFuncAttributeMaxDynamicSharedMemorySize, SMEM_BYTES);
    fnn_mma_kernel<<<GRID, NT, SMEM_BYTES>>>(
        x_in, weight, ag, W1, b3, W2, W1n, b3n, W2n, max_os_l, out);

    fnn_stencil_kernel<<<NSITE / 256, 256>>>(sigma_l, out);
}